// round 2
// baseline (speedup 1.0000x reference)
#include <cuda_runtime.h>
#include <cstdint>

#define F_IN  512
#define HID   128
#define MAXN  50000
#define MAXE  800000

// ---------- scratch (device globals; no allocation allowed) ----------
__device__ float    g_u1[F_IN];
__device__ float    g_u2[F_IN];
__device__ float    g_C;            // w1.gcn_b + w2.gcn_b + mlp_b
__device__ float    g_s1[MAXN];
__device__ float    g_s2[MAXN];
__device__ float    g_a[MAXN];
__device__ float    g_b[MAXN];
__device__ unsigned g_m[MAXN];      // encoded segment max
__device__ float    g_sum[MAXN];
__device__ float    g_temp[MAXE];
__device__ int      g_is64;         // 1 if v_indices is int64, 0 if int32

// monotonic float<->uint encoding for atomicMax over signed floats
__device__ __forceinline__ unsigned enc_f(float f) {
    unsigned u = __float_as_uint(f);
    return (u & 0x80000000u) ? ~u : (u | 0x80000000u);
}
__device__ __forceinline__ float dec_f(unsigned u) {
    return (u & 0x80000000u) ? __uint_as_float(u ^ 0x80000000u)
                             : __uint_as_float(~u);
}

// fetch index with dtype selected by probe; clamp defensively (never trap)
__device__ __forceinline__ int load_idx(const void* idx, int E, int which,
                                        int e, int N) {
    long long v;
    if (g_is64) v = ((const long long*)idx)[(size_t)which * E + e];
    else        v = ((const int*)idx)[(size_t)which * E + e];
    if (v < 0) v = 0;
    if (v >= N) v = N - 1;
    return (int)v;
}

// ---------- kernel 0: probe index dtype ----------
__global__ void probe_kernel(const void* idx, int E, int N) {
    // int32 data read as int64 packs two random values -> almost surely >= N.
    // int64 data read as int64 gives values in [0, N). Check first 256.
    int n = E < 256 ? E : 256;
    const long long* p = (const long long*)idx;
    int ok64 = 1;
    for (int i = 0; i < n; i++) {
        long long v = p[i];
        if (v < 0 || v >= N) { ok64 = 0; break; }
    }
    g_is64 = ok64;
}

// ---------- kernel 1: u1 = W @ w1, u2 = W @ w2, C = bias const ----------
__global__ void prep_kernel(const float* __restrict__ gcn_w,
                            const float* __restrict__ gcn_b,
                            const float* __restrict__ mlp_w,
                            const float* __restrict__ mlp_b) {
    int k = threadIdx.x;              // 0..511
    const float* wrow = gcn_w + k * HID;
    float u1 = 0.f, u2 = 0.f;
    #pragma unroll 8
    for (int h = 0; h < HID; h++) {
        float w = wrow[h];
        u1 += w * mlp_w[h];
        u2 += w * mlp_w[HID + h];
    }
    g_u1[k] = u1;
    g_u2[k] = u2;

    __shared__ float red[F_IN];
    float cb = 0.f;
    if (k < HID) cb = gcn_b[k] * (mlp_w[k] + mlp_w[HID + k]);
    red[k] = cb;
    __syncthreads();
    for (int s = F_IN / 2; s > 0; s >>= 1) {
        if (k < s) red[k] += red[k + s];
        __syncthreads();
    }
    if (k == 0) g_C = red[0] + mlp_b[0];
}

// ---------- kernel 2: init node accumulators ----------
__global__ void init_kernel(int N) {
    int i = blockIdx.x * blockDim.x + threadIdx.x;
    if (i < N) {
        g_a[i] = 0.f;
        g_b[i] = 0.f;
        g_m[i] = 0u;     // below enc of any finite float
        g_sum[i] = 0.f;
    }
}

// ---------- kernel 3: GEMV  s1 = feat@u1, s2 = feat@u2 (1 warp / row) ----------
__global__ void __launch_bounds__(256) gemv_kernel(const float* __restrict__ feat, int N) {
    __shared__ float4 su1[F_IN / 4];
    __shared__ float4 su2[F_IN / 4];
    for (int i = threadIdx.x; i < F_IN / 4; i += blockDim.x) {
        su1[i] = reinterpret_cast<const float4*>(g_u1)[i];
        su2[i] = reinterpret_cast<const float4*>(g_u2)[i];
    }
    __syncthreads();

    int warp = threadIdx.x >> 5, lane = threadIdx.x & 31;
    int row = blockIdx.x * 8 + warp;
    if (row >= N) return;

    const float4* f4 = reinterpret_cast<const float4*>(feat + (size_t)row * F_IN);
    float a1 = 0.f, a2 = 0.f;
    #pragma unroll
    for (int j = 0; j < 4; j++) {
        int idx = lane + 32 * j;
        float4 v  = f4[idx];
        float4 w1 = su1[idx];
        float4 w2 = su2[idx];
        a1 += v.x * w1.x + v.y * w1.y + v.z * w1.z + v.w * w1.w;
        a2 += v.x * w2.x + v.y * w2.y + v.z * w2.z + v.w * w2.w;
    }
    #pragma unroll
    for (int o = 16; o > 0; o >>= 1) {
        a1 += __shfl_down_sync(0xFFFFFFFFu, a1, o);
        a2 += __shfl_down_sync(0xFFFFFFFFu, a2, o);
    }
    if (lane == 0) {
        g_s1[row] = a1;
        g_s2[row] = a2;
    }
}

// ---------- kernel 4: a[row] += v*s1[col], b[row] += v*s2[col] ----------
__global__ void edge1_kernel(const void* __restrict__ idx,
                             const float* __restrict__ vvals, int E, int N) {
    int e = blockIdx.x * blockDim.x + threadIdx.x;
    if (e >= E) return;
    int r = load_idx(idx, E, 0, e, N);
    int c = load_idx(idx, E, 1, e, N);
    float v = vvals[e];
    atomicAdd(&g_a[r], v * g_s1[c]);
    atomicAdd(&g_b[r], v * g_s2[c]);
}

// ---------- kernel 5: temp + segment max ----------
__global__ void edge2_kernel(const void* __restrict__ idx, int E, int N) {
    int e = blockIdx.x * blockDim.x + threadIdx.x;
    if (e >= E) return;
    int r = load_idx(idx, E, 0, e, N);
    int c = load_idx(idx, E, 1, e, N);
    float t = g_a[r] + g_b[c] + g_C;
    g_temp[e] = t;
    atomicMax(&g_m[r], enc_f(t));
}

// ---------- kernel 6: exp + segment sum ----------
__global__ void edge3_kernel(const void* __restrict__ idx, int E, int N) {
    int e = blockIdx.x * blockDim.x + threadIdx.x;
    if (e >= E) return;
    int r = load_idx(idx, E, 0, e, N);
    float ex = __expf(g_temp[e] - dec_f(g_m[r]));
    atomicAdd(&g_sum[r], ex);
}

// ---------- kernel 7: output ----------
__global__ void edge4_kernel(const void* __restrict__ idx,
                             const float* __restrict__ vvals,
                             float* __restrict__ out, int E, int N) {
    int e = blockIdx.x * blockDim.x + threadIdx.x;
    if (e >= E) return;
    int r = load_idx(idx, E, 0, e, N);
    float ex = __expf(g_temp[e] - dec_f(g_m[r]));
    out[e] = vvals[e] + ex / g_sum[r];
}

extern "C" void kernel_launch(void* const* d_in, const int* in_sizes, int n_in,
                              void* d_out, int out_size) {
    // metadata order: v_ori_vals[E], feat[N*F_IN], v_indices[2E],
    //                 (num_node?), gcn_w, gcn_b, mlp_w, mlp_b
    const float* vvals = (const float*)d_in[0];
    const float* feat  = (const float*)d_in[1];
    const void*  idx   = d_in[2];
    int base = (n_in >= 8) ? 4 : 3;   // skip num_node scalar if present
    const float* gcn_w = (const float*)d_in[base + 0];
    const float* gcn_b = (const float*)d_in[base + 1];
    const float* mlp_w = (const float*)d_in[base + 2];
    const float* mlp_b = (const float*)d_in[base + 3];
    float*       out   = (float*)d_out;

    int E   = in_sizes[0];
    int hid = in_sizes[base + 1];        // 128
    int fin = in_sizes[base + 0] / hid;  // 512
    int N   = in_sizes[1] / fin;

    probe_kernel<<<1, 1>>>(idx, E, N);
    prep_kernel<<<1, F_IN>>>(gcn_w, gcn_b, mlp_w, mlp_b);
    init_kernel<<<(N + 255) / 256, 256>>>(N);
    gemv_kernel<<<(N + 7) / 8, 256>>>(feat, N);

    int eb = (E + 255) / 256;
    edge1_kernel<<<eb, 256>>>(idx, vvals, E, N);
    edge2_kernel<<<eb, 256>>>(idx, E, N);
    edge3_kernel<<<eb, 256>>>(idx, E, N);
    edge4_kernel<<<eb, 256>>>(idx, vvals, out, E, N);
}